// round 10
// baseline (speedup 1.0000x reference)
#include <cuda_runtime.h>
#include <cuda_bf16.h>
#include <mma.h>
#include <math.h>

using namespace nvcuda;

#define NN   100000
#define EE   1600000
#define DIM  128

// Scratch (static device globals: no allocations allowed; zero-initialized)
__device__ float g_dis[NN];
__device__ float g_h [(size_t)NN * DIM];   // hs = (A@W)*dis of current layer
__device__ float g_a [(size_t)NN * DIM];   // combined activation (next layer input)
__device__ int   g_cnt[NN];                // in-degree histogram (re-zeroed each run)
__device__ int   g_rowptr[NN + 1];         // CSR row pointers (by dst)
__device__ int   g_cursor[NN];             // fill cursors
__device__ int   g_colsrc[EE];             // src node id per CSR slot
__device__ int   g_blocksum[1024];         // per-block partial sums for scan
// Split weights (bf16 hi/lo)
__device__ __nv_bfloat16 g_W0h[16384], g_W0l[16384];
__device__ __nv_bfloat16 g_W1h[16384], g_W1l[16384];
__device__ __nv_bfloat16 g_W2h[8192],  g_W2l[8192];

__device__ __forceinline__ void split_bf16(float v, __nv_bfloat16& h, __nv_bfloat16& l) {
    h = __float2bfloat16(v);
    l = __float2bfloat16(v - __bfloat162float(h));
}

// ---------------------------------------------------------------------------
// Weight split: W(fp32) -> Wh + Wl (bf16)
// ---------------------------------------------------------------------------
__global__ void split_w_kernel(const float* __restrict__ W, __nv_bfloat16* __restrict__ Wh,
                               __nv_bfloat16* __restrict__ Wl, int n) {
    int i = blockIdx.x * blockDim.x + threadIdx.x;
    if (i < n) {
        __nv_bfloat16 h, l;
        split_bf16(W[i], h, l);
        Wh[i] = h; Wl[i] = l;
    }
}

// in-degree histogram (cnt must be zero on entry; scan_add re-zeroes it)
__global__ void count_kernel(const int* __restrict__ dst, int* cnt, int e) {
    int i = blockIdx.x * blockDim.x + threadIdx.x;
    if (i < e) atomicAdd(&cnt[dst[i]], 1);
}

// dis = rsqrt(deg+1) -- only needs cnt; unblocks gemm0 early
__global__ void dis_kernel(const int* __restrict__ cnt, float* __restrict__ dis, int n) {
    int i = blockIdx.x * blockDim.x + threadIdx.x;
    if (i < n) dis[i] = rsqrtf((float)cnt[i] + 1.0f);
}

// ---------------------------------------------------------------------------
// Multi-block exclusive scan, phase 1
// ---------------------------------------------------------------------------
__global__ __launch_bounds__(1024) void scan_block_kernel(const int* __restrict__ cnt,
                                                          int* __restrict__ rowptr,
                                                          int* __restrict__ blocksum, int n) {
    __shared__ int wsum[32];
    const int tid = threadIdx.x, lane = tid & 31, wid = tid >> 5;
    int i = blockIdx.x * 1024 + tid;
    int v = (i < n) ? cnt[i] : 0;
    int x = v;
#pragma unroll
    for (int off = 1; off < 32; off <<= 1) {
        int t = __shfl_up_sync(0xffffffffu, x, off);
        if (lane >= off) x += t;
    }
    if (lane == 31) wsum[wid] = x;
    __syncthreads();
    if (wid == 0) {
        int w = wsum[lane];
#pragma unroll
        for (int off = 1; off < 32; off <<= 1) {
            int t = __shfl_up_sync(0xffffffffu, w, off);
            if (lane >= off) w += t;
        }
        wsum[lane] = w;
    }
    __syncthreads();
    int excl = x - v + (wid ? wsum[wid - 1] : 0);
    if (i < n) rowptr[i] = excl;
    if (tid == 1023) blocksum[blockIdx.x] = wsum[31];
}

__global__ void scan_carry_kernel(int* blocksum, int nb) {
    if (threadIdx.x == 0) {
        int acc = 0;
        for (int i = 0; i < nb; i++) { int v = blocksum[i]; blocksum[i] = acc; acc += v; }
    }
}

// add carries -> rowptr & cursor; also re-zero cnt for the next graph replay
__global__ void scan_add_kernel(int* __restrict__ rowptr, const int* __restrict__ blocksum,
                                int* __restrict__ cnt, int* __restrict__ cur, int n, int e) {
    int i = blockIdx.x * blockDim.x + threadIdx.x;
    if (i < n) {
        int r = rowptr[i] + blocksum[i >> 10];
        rowptr[i] = r;
        cur[i]    = r;
        cnt[i]    = 0;
    }
    if (i == 0) rowptr[n] = e;
}

__global__ void fill_kernel(const int* __restrict__ src, const int* __restrict__ dst,
                            int* __restrict__ cur, int* __restrict__ colsrc, int e) {
    int i = blockIdx.x * blockDim.x + threadIdx.x;
    if (i < e) {
        int pos = atomicAdd(&cur[dst[i]], 1);
        colsrc[pos] = src[i];
    }
}

// ---------------------------------------------------------------------------
// Tensor-core GEMM v2 (bf16 split, fp32-equivalent accuracy):
//   C = A[M,128] @ W[128,BN] ; hs = C * dis[row]
// BM=128, 256 threads = 8 warps (4m x 2n), warp tile 32 x (BN/2).
// Full W (hi+lo) staged in smem ONCE; A split per 16-k stage, double-buffered.
// ---------------------------------------------------------------------------
template <int BN>
__global__ __launch_bounds__(256, 2) void gemm_tc_kernel(
    const float* __restrict__ A,
    const __nv_bfloat16* __restrict__ Bh_g,
    const __nv_bfloat16* __restrict__ Bl_g,
    const float* __restrict__ dis,
    float* __restrict__ hs_out, int M)
{
    constexpr int WN  = BN / 2;
    constexpr int FN  = WN / 16;
    constexpr int LDA = 24;
    constexpr int LDB = BN + 8;
    constexpr int ASZ = 128 * LDA;

    extern __shared__ __align__(16) unsigned char smem_raw[];
    __nv_bfloat16* Ab = (__nv_bfloat16*)smem_raw;        // 4 buffers: h0,l0,h1,l1
    __nv_bfloat16* Bh = Ab + 4 * ASZ;
    __nv_bfloat16* Bl = Bh + 128 * LDB;

    const int tid  = threadIdx.x;
    const int wid  = tid >> 5;
    const int wm   = wid & 3;
    const int wn   = wid >> 2;
    const int row0 = blockIdx.x * 128;

    constexpr int ELEMS = 128 * BN;
    for (int e = tid * 8; e < ELEMS; e += 256 * 8) {
        int r = e / BN, c = e % BN;
        *(uint4*)&Bh[r * LDB + c] = *(const uint4*)&Bh_g[e];
        *(uint4*)&Bl[r * LDB + c] = *(const uint4*)&Bl_g[e];
    }

    wmma::fragment<wmma::accumulator, 16, 16, 16, float> acc[2][FN];
#pragma unroll
    for (int i = 0; i < 2; i++)
#pragma unroll
        for (int j = 0; j < FN; j++) wmma::fill_fragment(acc[i][j], 0.f);

    const int ar   = tid >> 1;
    const int ak   = (tid & 1) * 8;
    const int arow = row0 + ar;

    float4 v0 = make_float4(0.f, 0.f, 0.f, 0.f), v1 = v0;
    if (arow < M) {
        v0 = *(const float4*)(A + (size_t)arow * 128 + ak);
        v1 = *(const float4*)(A + (size_t)arow * 128 + ak + 4);
    }

    for (int s = 0; s < 8; s++) {
        __nv_bfloat16* pAh = Ab + (s & 1) * 2 * ASZ;
        __nv_bfloat16* pAl = pAh + ASZ;
        {
            __nv_bfloat16 h, l;
            split_bf16(v0.x, h, l); pAh[ar * LDA + ak + 0] = h; pAl[ar * LDA + ak + 0] = l;
            split_bf16(v0.y, h, l); pAh[ar * LDA + ak + 1] = h; pAl[ar * LDA + ak + 1] = l;
            split_bf16(v0.z, h, l); pAh[ar * LDA + ak + 2] = h; pAl[ar * LDA + ak + 2] = l;
            split_bf16(v0.w, h, l); pAh[ar * LDA + ak + 3] = h; pAl[ar * LDA + ak + 3] = l;
            split_bf16(v1.x, h, l); pAh[ar * LDA + ak + 4] = h; pAl[ar * LDA + ak + 4] = l;
            split_bf16(v1.y, h, l); pAh[ar * LDA + ak + 5] = h; pAl[ar * LDA + ak + 5] = l;
            split_bf16(v1.z, h, l); pAh[ar * LDA + ak + 6] = h; pAl[ar * LDA + ak + 6] = l;
            split_bf16(v1.w, h, l); pAh[ar * LDA + ak + 7] = h; pAl[ar * LDA + ak + 7] = l;
        }
        __syncthreads();

        if (s < 7 && arow < M) {
            v0 = *(const float4*)(A + (size_t)arow * 128 + (s + 1) * 16 + ak);
            v1 = *(const float4*)(A + (size_t)arow * 128 + (s + 1) * 16 + ak + 4);
        }

        wmma::fragment<wmma::matrix_a, 16, 16, 16, __nv_bfloat16, wmma::row_major> fa_h[2], fa_l[2];
#pragma unroll
        for (int i = 0; i < 2; i++) {
            wmma::load_matrix_sync(fa_h[i], pAh + (wm * 32 + i * 16) * LDA, LDA);
            wmma::load_matrix_sync(fa_l[i], pAl + (wm * 32 + i * 16) * LDA, LDA);
        }
#pragma unroll
        for (int j = 0; j < FN; j++) {
            wmma::fragment<wmma::matrix_b, 16, 16, 16, __nv_bfloat16, wmma::row_major> fb_h, fb_l;
            wmma::load_matrix_sync(fb_h, Bh + (s * 16) * LDB + wn * WN + j * 16, LDB);
            wmma::load_matrix_sync(fb_l, Bl + (s * 16) * LDB + wn * WN + j * 16, LDB);
#pragma unroll
            for (int i = 0; i < 2; i++) {
                wmma::mma_sync(acc[i][j], fa_h[i], fb_h, acc[i][j]);
                wmma::mma_sync(acc[i][j], fa_h[i], fb_l, acc[i][j]);
                wmma::mma_sync(acc[i][j], fa_l[i], fb_h, acc[i][j]);
            }
        }
    }

    __syncthreads();
    float* Cs = (float*)smem_raw;
#pragma unroll
    for (int i = 0; i < 2; i++)
#pragma unroll
        for (int j = 0; j < FN; j++)
            wmma::store_matrix_sync(Cs + (wm * 32 + i * 16) * BN + wn * WN + j * 16,
                                    acc[i][j], BN, wmma::mem_row_major);
    __syncthreads();

    constexpr int QB = BN / 4;
    for (int i = tid; i < 128 * QB; i += 256) {
        int r = i / QB, c = (i % QB) * 4;
        int row = row0 + r;
        if (row < M) {
            float dd = __ldg(dis + row);
            float4 o = *(float4*)&Cs[r * BN + c];
            o.x *= dd; o.y *= dd; o.z *= dd; o.w *= dd;
            *(float4*)(hs_out + (size_t)row * BN + c) = o;
        }
    }
}

// ---------------------------------------------------------------------------
// Aggregation + combine (CSR segment sum, no atomics):
//   outA[d,f] = relu( dis[d] * ( hs[d,f] + sum_{s in N(d)} hs[s,f] ) + b[f] )
// ---------------------------------------------------------------------------
template <int F>
__global__ __launch_bounds__(F) void agg_combine_kernel(
    const float* __restrict__ hs, const int* __restrict__ rowptr,
    const int* __restrict__ colsrc, const float* __restrict__ dis,
    const float* __restrict__ bias, float* __restrict__ outA, int n)
{
    int node = blockIdx.x;
    int f    = threadIdx.x;
    int beg  = __ldg(rowptr + node);
    int end  = __ldg(rowptr + node + 1);

    float s0 = __ldg(hs + (size_t)node * F + f);
    float s1 = 0.f, s2 = 0.f, s3 = 0.f;
    int p = beg;
    for (; p + 4 <= end; p += 4) {
        int i0 = __ldg(colsrc + p + 0);
        int i1 = __ldg(colsrc + p + 1);
        int i2 = __ldg(colsrc + p + 2);
        int i3 = __ldg(colsrc + p + 3);
        s0 += __ldg(hs + (size_t)i0 * F + f);
        s1 += __ldg(hs + (size_t)i1 * F + f);
        s2 += __ldg(hs + (size_t)i2 * F + f);
        s3 += __ldg(hs + (size_t)i3 * F + f);
    }
    for (; p < end; ++p)
        s0 += __ldg(hs + (size_t)__ldg(colsrc + p) * F + f);

    float sum = (s0 + s1) + (s2 + s3);
    outA[(size_t)node * F + f] = fmaxf(fmaf(__ldg(dis + node), sum, __ldg(bias + f)), 0.f);
}

// ---------------------------------------------------------------------------
// Fused final layer: aggregation + combine + relu + log_softmax (F=64)
// One 64-thread block per node.
// ---------------------------------------------------------------------------
__global__ __launch_bounds__(64) void agg_lsm_kernel(
    const float* __restrict__ hs, const int* __restrict__ rowptr,
    const int* __restrict__ colsrc, const float* __restrict__ dis,
    const float* __restrict__ bias, float* __restrict__ out, int n)
{
    constexpr int F = 64;
    int node = blockIdx.x;
    int f    = threadIdx.x;
    int lane = f & 31, w = f >> 5;
    int beg  = __ldg(rowptr + node);
    int end  = __ldg(rowptr + node + 1);

    float s0 = __ldg(hs + (size_t)node * F + f);
    float s1 = 0.f, s2 = 0.f, s3 = 0.f;
    int p = beg;
    for (; p + 4 <= end; p += 4) {
        int i0 = __ldg(colsrc + p + 0);
        int i1 = __ldg(colsrc + p + 1);
        int i2 = __ldg(colsrc + p + 2);
        int i3 = __ldg(colsrc + p + 3);
        s0 += __ldg(hs + (size_t)i0 * F + f);
        s1 += __ldg(hs + (size_t)i1 * F + f);
        s2 += __ldg(hs + (size_t)i2 * F + f);
        s3 += __ldg(hs + (size_t)i3 * F + f);
    }
    for (; p < end; ++p)
        s0 += __ldg(hs + (size_t)__ldg(colsrc + p) * F + f);

    float v = fmaxf(fmaf(__ldg(dis + node), (s0 + s1) + (s2 + s3), __ldg(bias + f)), 0.f);

    __shared__ float sred[2];
    float m = v;
#pragma unroll
    for (int off = 16; off > 0; off >>= 1)
        m = fmaxf(m, __shfl_xor_sync(0xffffffffu, m, off));
    if (lane == 0) sred[w] = m;
    __syncthreads();
    float M2 = fmaxf(sred[0], sred[1]);
    __syncthreads();

    float e = expf(v - M2);
    float s = e;
#pragma unroll
    for (int off = 16; off > 0; off >>= 1)
        s += __shfl_xor_sync(0xffffffffu, s, off);
    if (lane == 0) sred[w] = s;
    __syncthreads();
    float S = sred[0] + sred[1];

    out[(size_t)node * F + f] = v - M2 - logf(S);
}

// ---------------------------------------------------------------------------
// Launch
// ---------------------------------------------------------------------------
extern "C" void kernel_launch(void* const* d_in, const int* in_sizes, int n_in,
                              void* d_out, int out_size) {
    const float* x  = (const float*)d_in[0];
    const int*   ei = (const int*)d_in[1];
    const float* W0 = (const float*)d_in[2];
    const float* b0 = (const float*)d_in[3];
    const float* W1 = (const float*)d_in[4];
    const float* b1 = (const float*)d_in[5];
    const float* W2 = (const float*)d_in[6];
    const float* b2 = (const float*)d_in[7];
    float* out = (float*)d_out;

    const int E = in_sizes[1] / 2;
    const int N = in_sizes[0] / DIM;
    const int* src = ei;
    const int* dst = ei + E;

    float *p_dis, *p_h, *p_a;
    int *p_cnt, *p_rowptr, *p_cursor, *p_colsrc, *p_blocksum;
    __nv_bfloat16 *p_W0h, *p_W0l, *p_W1h, *p_W1l, *p_W2h, *p_W2l;
    cudaGetSymbolAddress((void**)&p_dis,      g_dis);
    cudaGetSymbolAddress((void**)&p_h,        g_h);
    cudaGetSymbolAddress((void**)&p_a,        g_a);
    cudaGetSymbolAddress((void**)&p_cnt,      g_cnt);
    cudaGetSymbolAddress((void**)&p_rowptr,   g_rowptr);
    cudaGetSymbolAddress((void**)&p_cursor,   g_cursor);
    cudaGetSymbolAddress((void**)&p_colsrc,   g_colsrc);
    cudaGetSymbolAddress((void**)&p_blocksum, g_blocksum);
    cudaGetSymbolAddress((void**)&p_W0h, g_W0h); cudaGetSymbolAddress((void**)&p_W0l, g_W0l);
    cudaGetSymbolAddress((void**)&p_W1h, g_W1h); cudaGetSymbolAddress((void**)&p_W1l, g_W1l);
    cudaGetSymbolAddress((void**)&p_W2h, g_W2h); cudaGetSymbolAddress((void**)&p_W2l, g_W2l);

    static cudaStream_t s_prep = nullptr;
    static cudaEvent_t  ev_dis = nullptr, ev_fill = nullptr;
    if (s_prep == nullptr) {
        cudaStreamCreateWithFlags(&s_prep, cudaStreamNonBlocking);
        cudaEventCreateWithFlags(&ev_dis,  cudaEventDisableTiming);
        cudaEventCreateWithFlags(&ev_fill, cudaEventDisableTiming);
    }

    const int smem128 = (4 * 128 * 24 + 2 * 128 * 136) * 2;   // 94208 B
    const int smem64  = (4 * 128 * 24 + 2 * 128 * 72)  * 2;   // 61440 B
    cudaFuncSetAttribute(gemm_tc_kernel<128>, cudaFuncAttributeMaxDynamicSharedMemorySize, smem128);
    cudaFuncSetAttribute(gemm_tc_kernel<64>,  cudaFuncAttributeMaxDynamicSharedMemorySize, smem64);

    const int T = 256;
    const int nb = (N + 1023) / 1024;
    const int gemm_blocks = (N + 127) / 128;

    // ---- main stream head (launches 1-6; #6 = gemm0 for ncu capture) ----
    split_w_kernel<<<64, 256>>>(W0, p_W0h, p_W0l, 16384);        // 1
    split_w_kernel<<<64, 256>>>(W1, p_W1h, p_W1l, 16384);        // 2
    split_w_kernel<<<32, 256>>>(W2, p_W2h, p_W2l, 8192);         // 3
    count_kernel<<<(E + T - 1) / T, T>>>(dst, p_cnt, E);         // 4  (cnt pre-zeroed)
    dis_kernel<<<(N + T - 1) / T, T>>>(p_cnt, p_dis, N);         // 5
    cudaEventRecord(ev_dis, 0);
    gemm_tc_kernel<128><<<gemm_blocks, 256, smem128>>>(x, p_W0h, p_W0l, p_dis, p_h, N); // 6

    // ---- prep stream: CSR build concurrent with gemm0 ----
    cudaStreamWaitEvent(s_prep, ev_dis, 0);   // cnt reads (scan) after dis read done
    scan_block_kernel<<<nb, 1024, 0, s_prep>>>(p_cnt, p_rowptr, p_blocksum, N);
    scan_carry_kernel<<<1, 32, 0, s_prep>>>(p_blocksum, nb);
    scan_add_kernel<<<(N + T - 1) / T, T, 0, s_prep>>>(p_rowptr, p_blocksum, p_cnt,
                                                       p_cursor, N, E);
    fill_kernel<<<(E + T - 1) / T, T, 0, s_prep>>>(src, dst, p_cursor, p_colsrc, E);
    cudaEventRecord(ev_fill, s_prep);

    // ---- main stream: join, then the rest of the network ----
    cudaStreamWaitEvent(0, ev_fill, 0);
    agg_combine_kernel<128><<<N, 128>>>(p_h, p_rowptr, p_colsrc, p_dis, b0, p_a, N);

    gemm_tc_kernel<128><<<gemm_blocks, 256, smem128>>>(p_a, p_W1h, p_W1l, p_dis, p_h, N);
    agg_combine_kernel<128><<<N, 128>>>(p_h, p_rowptr, p_colsrc, p_dis, b1, p_a, N);

    gemm_tc_kernel<64><<<gemm_blocks, 256, smem64>>>(p_a, p_W2h, p_W2l, p_dis, p_h, N);
    agg_lsm_kernel<<<N, 64>>>(p_h, p_rowptr, p_colsrc, p_dis, b2, out, N);
}

// round 11
// speedup vs baseline: 1.2898x; 1.2898x over previous
#include <cuda_runtime.h>
#include <cuda_bf16.h>
#include <mma.h>
#include <math.h>

using namespace nvcuda;

#define NN   100000
#define EE   1600000
#define DIM  128

// Scratch (static device globals: no allocations allowed; zero-initialized)
__device__ float g_dis[NN];
__device__ float g_h [(size_t)NN * DIM];             // hs = (A@W)*dis (fp32)
__device__ __nv_bfloat16 g_ah[(size_t)NN * DIM];     // activation hi (bf16)
__device__ __nv_bfloat16 g_al[(size_t)NN * DIM];     // activation lo (bf16)
__device__ int   g_cnt[NN];                          // in-degree histogram (re-zeroed per run)
__device__ int   g_rowptr[NN + 1];
__device__ int   g_cursor[NN];
__device__ int   g_colsrc[EE];
__device__ int   g_blocksum[1024];
// Split weights (bf16 hi/lo)
__device__ __nv_bfloat16 g_W0h[16384], g_W0l[16384];
__device__ __nv_bfloat16 g_W1h[16384], g_W1l[16384];
__device__ __nv_bfloat16 g_W2h[8192],  g_W2l[8192];

__device__ __forceinline__ void split_bf16(float v, __nv_bfloat16& h, __nv_bfloat16& l) {
    h = __float2bfloat16(v);
    l = __float2bfloat16(v - __bfloat162float(h));
}

// ---------------------------------------------------------------------------
// Generic fp32 -> bf16 hi/lo split (vectorized by float4)
// ---------------------------------------------------------------------------
__global__ void split_f32_kernel(const float* __restrict__ X, __nv_bfloat16* __restrict__ H,
                                 __nv_bfloat16* __restrict__ L, int n4) {
    int i = blockIdx.x * blockDim.x + threadIdx.x;
    if (i >= n4) return;
    float4 v = ((const float4*)X)[i];
    __nv_bfloat16 h0, h1, h2, h3, l0, l1, l2, l3;
    split_bf16(v.x, h0, l0); split_bf16(v.y, h1, l1);
    split_bf16(v.z, h2, l2); split_bf16(v.w, h3, l3);
    __nv_bfloat162* Hp = (__nv_bfloat162*)H;
    __nv_bfloat162* Lp = (__nv_bfloat162*)L;
    Hp[2 * i]     = __nv_bfloat162(h0, h1);
    Hp[2 * i + 1] = __nv_bfloat162(h2, h3);
    Lp[2 * i]     = __nv_bfloat162(l0, l1);
    Lp[2 * i + 1] = __nv_bfloat162(l2, l3);
}

// in-degree histogram (cnt zero on entry; scan_add re-zeroes it each run)
__global__ void count_kernel(const int* __restrict__ dst, int* cnt, int e) {
    int i = blockIdx.x * blockDim.x + threadIdx.x;
    if (i < e) atomicAdd(&cnt[dst[i]], 1);
}

// dis = rsqrt(deg+1)
__global__ void dis_kernel(const int* __restrict__ cnt, float* __restrict__ dis, int n) {
    int i = blockIdx.x * blockDim.x + threadIdx.x;
    if (i < n) dis[i] = rsqrtf((float)cnt[i] + 1.0f);
}

// ---------------------------------------------------------------------------
// Multi-block exclusive scan
// ---------------------------------------------------------------------------
__global__ __launch_bounds__(1024) void scan_block_kernel(const int* __restrict__ cnt,
                                                          int* __restrict__ rowptr,
                                                          int* __restrict__ blocksum, int n) {
    __shared__ int wsum[32];
    const int tid = threadIdx.x, lane = tid & 31, wid = tid >> 5;
    int i = blockIdx.x * 1024 + tid;
    int v = (i < n) ? cnt[i] : 0;
    int x = v;
#pragma unroll
    for (int off = 1; off < 32; off <<= 1) {
        int t = __shfl_up_sync(0xffffffffu, x, off);
        if (lane >= off) x += t;
    }
    if (lane == 31) wsum[wid] = x;
    __syncthreads();
    if (wid == 0) {
        int w = wsum[lane];
#pragma unroll
        for (int off = 1; off < 32; off <<= 1) {
            int t = __shfl_up_sync(0xffffffffu, w, off);
            if (lane >= off) w += t;
        }
        wsum[lane] = w;
    }
    __syncthreads();
    int excl = x - v + (wid ? wsum[wid - 1] : 0);
    if (i < n) rowptr[i] = excl;
    if (tid == 1023) blocksum[blockIdx.x] = wsum[31];
}

__global__ void scan_carry_kernel(int* blocksum, int nb) {
    if (threadIdx.x == 0) {
        int acc = 0;
        for (int i = 0; i < nb; i++) { int v = blocksum[i]; blocksum[i] = acc; acc += v; }
    }
}

// add carries -> rowptr & cursor; re-zero cnt for next replay
__global__ void scan_add_kernel(int* __restrict__ rowptr, const int* __restrict__ blocksum,
                                int* __restrict__ cnt, int* __restrict__ cur, int n, int e) {
    int i = blockIdx.x * blockDim.x + threadIdx.x;
    if (i < n) {
        int r = rowptr[i] + blocksum[i >> 10];
        rowptr[i] = r;
        cur[i]    = r;
        cnt[i]    = 0;
    }
    if (i == 0) rowptr[n] = e;
}

__global__ void fill_kernel(const int* __restrict__ src, const int* __restrict__ dst,
                            int* __restrict__ cur, int* __restrict__ colsrc, int e) {
    int i = blockIdx.x * blockDim.x + threadIdx.x;
    if (i < e) {
        int pos = atomicAdd(&cur[dst[i]], 1);
        colsrc[pos] = src[i];
    }
}

// ---------------------------------------------------------------------------
// Tensor-core GEMM v3: A pre-split to bf16 hi/lo in gmem (no in-kernel split)
//   C = A[M,128] @ W[128,BN] ; hs = C * dis[row]
// BM=128, 256 threads = 8 warps (4m x 2n), warp tile 32 x (BN/2).
// Full W (hi+lo) staged in smem once; A tiles double-buffered.
// ---------------------------------------------------------------------------
template <int BN>
__global__ __launch_bounds__(256, 2) void gemm_tc_kernel(
    const __nv_bfloat16* __restrict__ Ah_g,
    const __nv_bfloat16* __restrict__ Al_g,
    const __nv_bfloat16* __restrict__ Bh_g,
    const __nv_bfloat16* __restrict__ Bl_g,
    const float* __restrict__ dis,
    float* __restrict__ hs_out, int M)
{
    constexpr int WN  = BN / 2;
    constexpr int FN  = WN / 16;
    constexpr int LDA = 24;
    constexpr int LDB = BN + 8;
    constexpr int ASZ = 128 * LDA;

    extern __shared__ __align__(16) unsigned char smem_raw[];
    __nv_bfloat16* Ab = (__nv_bfloat16*)smem_raw;        // 4 buffers: h0,l0,h1,l1
    __nv_bfloat16* Bh = Ab + 4 * ASZ;
    __nv_bfloat16* Bl = Bh + 128 * LDB;

    const int tid  = threadIdx.x;
    const int wid  = tid >> 5;
    const int wm   = wid & 3;
    const int wn   = wid >> 2;
    const int row0 = blockIdx.x * 128;

    constexpr int ELEMS = 128 * BN;
    for (int e = tid * 8; e < ELEMS; e += 256 * 8) {
        int r = e / BN, c = e % BN;
        *(uint4*)&Bh[r * LDB + c] = *(const uint4*)&Bh_g[e];
        *(uint4*)&Bl[r * LDB + c] = *(const uint4*)&Bl_g[e];
    }

    wmma::fragment<wmma::accumulator, 16, 16, 16, float> acc[2][FN];
#pragma unroll
    for (int i = 0; i < 2; i++)
#pragma unroll
        for (int j = 0; j < FN; j++) wmma::fill_fragment(acc[i][j], 0.f);

    const int ar   = tid >> 1;         // 0..127
    const int ak   = (tid & 1) * 8;    // 0 or 8
    const int arow = row0 + ar;

    uint4 vh = make_uint4(0, 0, 0, 0), vl = vh;
    if (arow < M) {
        vh = *(const uint4*)(Ah_g + (size_t)arow * 128 + ak);
        vl = *(const uint4*)(Al_g + (size_t)arow * 128 + ak);
    }

    for (int s = 0; s < 8; s++) {
        __nv_bfloat16* pAh = Ab + (s & 1) * 2 * ASZ;
        __nv_bfloat16* pAl = pAh + ASZ;
        *(uint4*)&pAh[ar * LDA + ak] = vh;
        *(uint4*)&pAl[ar * LDA + ak] = vl;
        __syncthreads();

        if (s < 7 && arow < M) {
            vh = *(const uint4*)(Ah_g + (size_t)arow * 128 + (s + 1) * 16 + ak);
            vl = *(const uint4*)(Al_g + (size_t)arow * 128 + (s + 1) * 16 + ak);
        }

        wmma::fragment<wmma::matrix_a, 16, 16, 16, __nv_bfloat16, wmma::row_major> fa_h[2], fa_l[2];
#pragma unroll
        for (int i = 0; i < 2; i++) {
            wmma::load_matrix_sync(fa_h[i], pAh + (wm * 32 + i * 16) * LDA, LDA);
            wmma::load_matrix_sync(fa_l[i], pAl + (wm * 32 + i * 16) * LDA, LDA);
        }
#pragma unroll
        for (int j = 0; j < FN; j++) {
            wmma::fragment<wmma::matrix_b, 16, 16, 16, __nv_bfloat16, wmma::row_major> fb_h, fb_l;
            wmma::load_matrix_sync(fb_h, Bh + (s * 16) * LDB + wn * WN + j * 16, LDB);
            wmma::load_matrix_sync(fb_l, Bl + (s * 16) * LDB + wn * WN + j * 16, LDB);
#pragma unroll
            for (int i = 0; i < 2; i++) {
                wmma::mma_sync(acc[i][j], fa_h[i], fb_h, acc[i][j]);
                wmma::mma_sync(acc[i][j], fa_h[i], fb_l, acc[i][j]);
                wmma::mma_sync(acc[i][j], fa_l[i], fb_h, acc[i][j]);
            }
        }
        __syncthreads();
    }

    float* Cs = (float*)smem_raw;
#pragma unroll
    for (int i = 0; i < 2; i++)
#pragma unroll
        for (int j = 0; j < FN; j++)
            wmma::store_matrix_sync(Cs + (wm * 32 + i * 16) * BN + wn * WN + j * 16,
                                    acc[i][j], BN, wmma::mem_row_major);
    __syncthreads();

    constexpr int QB = BN / 4;
    for (int i = tid; i < 128 * QB; i += 256) {
        int r = i / QB, c = (i % QB) * 4;
        int row = row0 + r;
        if (row < M) {
            float dd = __ldg(dis + row);
            float4 o = *(float4*)&Cs[r * BN + c];
            o.x *= dd; o.y *= dd; o.z *= dd; o.w *= dd;
            *(float4*)(hs_out + (size_t)row * BN + c) = o;
        }
    }
}

// ---------------------------------------------------------------------------
// Aggregation + combine (CSR segment sum, no atomics), emits bf16 hi/lo:
//   v = relu( dis[d]*( hs[d,f] + sum hs[src,f] ) + b[f] ) ;  Ah/Al = split(v)
// ---------------------------------------------------------------------------
__global__ __launch_bounds__(128) void agg_combine_kernel(
    const float* __restrict__ hs, const int* __restrict__ rowptr,
    const int* __restrict__ colsrc, const float* __restrict__ dis,
    const float* __restrict__ bias,
    __nv_bfloat16* __restrict__ outH, __nv_bfloat16* __restrict__ outL, int n)
{
    constexpr int F = 128;
    int node = blockIdx.x;
    int f    = threadIdx.x;
    int beg  = __ldg(rowptr + node);
    int end  = __ldg(rowptr + node + 1);

    float s0 = __ldg(hs + (size_t)node * F + f);
    float s1 = 0.f, s2 = 0.f, s3 = 0.f;
    int p = beg;
    for (; p + 4 <= end; p += 4) {
        int i0 = __ldg(colsrc + p + 0);
        int i1 = __ldg(colsrc + p + 1);
        int i2 = __ldg(colsrc + p + 2);
        int i3 = __ldg(colsrc + p + 3);
        s0 += __ldg(hs + (size_t)i0 * F + f);
        s1 += __ldg(hs + (size_t)i1 * F + f);
        s2 += __ldg(hs + (size_t)i2 * F + f);
        s3 += __ldg(hs + (size_t)i3 * F + f);
    }
    for (; p < end; ++p)
        s0 += __ldg(hs + (size_t)__ldg(colsrc + p) * F + f);

    float v = fmaxf(fmaf(__ldg(dis + node), (s0 + s1) + (s2 + s3), __ldg(bias + f)), 0.f);
    __nv_bfloat16 h, l;
    split_bf16(v, h, l);
    outH[(size_t)node * F + f] = h;
    outL[(size_t)node * F + f] = l;
}

// ---------------------------------------------------------------------------
// Fused final layer: aggregation + combine + relu + log_softmax (F=64)
// ---------------------------------------------------------------------------
__global__ __launch_bounds__(64) void agg_lsm_kernel(
    const float* __restrict__ hs, const int* __restrict__ rowptr,
    const int* __restrict__ colsrc, const float* __restrict__ dis,
    const float* __restrict__ bias, float* __restrict__ out, int n)
{
    constexpr int F = 64;
    int node = blockIdx.x;
    int f    = threadIdx.x;
    int lane = f & 31, w = f >> 5;
    int beg  = __ldg(rowptr + node);
    int end  = __ldg(rowptr + node + 1);

    float s0 = __ldg(hs + (size_t)node * F + f);
    float s1 = 0.f, s2 = 0.f, s3 = 0.f;
    int p = beg;
    for (; p + 4 <= end; p += 4) {
        int i0 = __ldg(colsrc + p + 0);
        int i1 = __ldg(colsrc + p + 1);
        int i2 = __ldg(colsrc + p + 2);
        int i3 = __ldg(colsrc + p + 3);
        s0 += __ldg(hs + (size_t)i0 * F + f);
        s1 += __ldg(hs + (size_t)i1 * F + f);
        s2 += __ldg(hs + (size_t)i2 * F + f);
        s3 += __ldg(hs + (size_t)i3 * F + f);
    }
    for (; p < end; ++p)
        s0 += __ldg(hs + (size_t)__ldg(colsrc + p) * F + f);

    float v = fmaxf(fmaf(__ldg(dis + node), (s0 + s1) + (s2 + s3), __ldg(bias + f)), 0.f);

    __shared__ float sred[2];
    float m = v;
#pragma unroll
    for (int off = 16; off > 0; off >>= 1)
        m = fmaxf(m, __shfl_xor_sync(0xffffffffu, m, off));
    if (lane == 0) sred[w] = m;
    __syncthreads();
    float M2 = fmaxf(sred[0], sred[1]);
    __syncthreads();

    float e = expf(v - M2);
    float s = e;
#pragma unroll
    for (int off = 16; off > 0; off >>= 1)
        s += __shfl_xor_sync(0xffffffffu, s, off);
    if (lane == 0) sred[w] = s;
    __syncthreads();
    float S = sred[0] + sred[1];

    out[(size_t)node * F + f] = v - M2 - logf(S);
}

// ---------------------------------------------------------------------------
// Launch (single stream, sequential; gemm0 is launch #6 for ncu capture)
// ---------------------------------------------------------------------------
extern "C" void kernel_launch(void* const* d_in, const int* in_sizes, int n_in,
                              void* d_out, int out_size) {
    const float* x  = (const float*)d_in[0];
    const int*   ei = (const int*)d_in[1];
    const float* W0 = (const float*)d_in[2];
    const float* b0 = (const float*)d_in[3];
    const float* W1 = (const float*)d_in[4];
    const float* b1 = (const float*)d_in[5];
    const float* W2 = (const float*)d_in[6];
    const float* b2 = (const float*)d_in[7];
    float* out = (float*)d_out;

    const int E = in_sizes[1] / 2;
    const int N = in_sizes[0] / DIM;
    const int* src = ei;
    const int* dst = ei + E;

    float *p_dis, *p_h;
    __nv_bfloat16 *p_ah, *p_al;
    int *p_cnt, *p_rowptr, *p_cursor, *p_colsrc, *p_blocksum;
    __nv_bfloat16 *p_W0h, *p_W0l, *p_W1h, *p_W1l, *p_W2h, *p_W2l;
    cudaGetSymbolAddress((void**)&p_dis,      g_dis);
    cudaGetSymbolAddress((void**)&p_h,        g_h);
    cudaGetSymbolAddress((void**)&p_ah,       g_ah);
    cudaGetSymbolAddress((void**)&p_al,       g_al);
    cudaGetSymbolAddress((void**)&p_cnt,      g_cnt);
    cudaGetSymbolAddress((void**)&p_rowptr,   g_rowptr);
    cudaGetSymbolAddress((void**)&p_cursor,   g_cursor);
    cudaGetSymbolAddress((void**)&p_colsrc,   g_colsrc);
    cudaGetSymbolAddress((void**)&p_blocksum, g_blocksum);
    cudaGetSymbolAddress((void**)&p_W0h, g_W0h); cudaGetSymbolAddress((void**)&p_W0l, g_W0l);
    cudaGetSymbolAddress((void**)&p_W1h, g_W1h); cudaGetSymbolAddress((void**)&p_W1l, g_W1l);
    cudaGetSymbolAddress((void**)&p_W2h, g_W2h); cudaGetSymbolAddress((void**)&p_W2l, g_W2l);

    const int smem128 = (4 * 128 * 24 + 2 * 128 * 136) * 2;   // 94208 B
    const int smem64  = (4 * 128 * 24 + 2 * 128 * 72)  * 2;   // 61440 B
    cudaFuncSetAttribute(gemm_tc_kernel<128>, cudaFuncAttributeMaxDynamicSharedMemorySize, smem128);
    cudaFuncSetAttribute(gemm_tc_kernel<64>,  cudaFuncAttributeMaxDynamicSharedMemorySize, smem64);

    const int T = 256;
    const int nb = (N + 1023) / 1024;
    const int gemm_blocks = (N + 127) / 128;
    const int x4 = N * 32;   // float4 count of x

    // 1-5: prerequisites of gemm0 (+ one independent prep kernel)
    count_kernel<<<(E + T - 1) / T, T>>>(dst, p_cnt, E);                     // 1
    dis_kernel<<<(N + T - 1) / T, T>>>(p_cnt, p_dis, N);                     // 2
    split_f32_kernel<<<(x4 + T - 1) / T, T>>>(x, p_ah, p_al, x4);            // 3
    split_f32_kernel<<<(4096 + T - 1) / T, T>>>(W0, p_W0h, p_W0l, 4096);     // 4
    scan_block_kernel<<<nb, 1024>>>(p_cnt, p_rowptr, p_blocksum, N);         // 5

    // 6: layer-0 GEMM (ncu -s 5 -c 1 captures this)
    gemm_tc_kernel<128><<<gemm_blocks, 256, smem128>>>(p_ah, p_al, p_W0h, p_W0l,
                                                       p_dis, p_h, N);       // 6

    // rest of CSR build + remaining weight splits
    split_f32_kernel<<<(4096 + T - 1) / T, T>>>(W1, p_W1h, p_W1l, 4096);
    split_f32_kernel<<<(2048 + T - 1) / T, T>>>(W2, p_W2h, p_W2l, 2048);
    scan_carry_kernel<<<1, 32>>>(p_blocksum, nb);
    scan_add_kernel<<<(N + T - 1) / T, T>>>(p_rowptr, p_blocksum, p_cnt, p_cursor, N, E);
    fill_kernel<<<(E + T - 1) / T, T>>>(src, dst, p_cursor, p_colsrc, E);

    // Layer 0 combine -> (Ah, Al)
    agg_combine_kernel<<<N, 128>>>(p_h, p_rowptr, p_colsrc, p_dis, b0, p_ah, p_al, N);

    // Layer 1
    gemm_tc_kernel<128><<<gemm_blocks, 256, smem128>>>(p_ah, p_al, p_W1h, p_W1l,
                                                       p_dis, p_h, N);
    agg_combine_kernel<<<N, 128>>>(p_h, p_rowptr, p_colsrc, p_dis, b1, p_ah, p_al, N);

    // Layer 2 (64 cols) + fused log_softmax
    gemm_tc_kernel<64><<<gemm_blocks, 256, smem64>>>(p_ah, p_al, p_W2h, p_W2l,
                                                     p_dis, p_h, N);
    agg_lsm_kernel<<<N, 64>>>(p_h, p_rowptr, p_colsrc, p_dis, b2, out, N);
}

// round 14
// speedup vs baseline: 1.2995x; 1.0075x over previous
#include <cuda_runtime.h>
#include <cuda_bf16.h>
#include <mma.h>
#include <math.h>

using namespace nvcuda;

#define NN   100000
#define EE   1600000
#define DIM  128

// Scratch (static device globals: no allocations allowed; zero-initialized)
__device__ float g_dis[NN];
__device__ float g_h [(size_t)NN * DIM];   // hs = (A@W)*dis of current layer
__device__ float g_a [(size_t)NN * DIM];   // combined activation (next layer input)
__device__ int   g_cnt[NN];                // in-degree histogram (re-zeroed each run)
__device__ int   g_rowptr[NN + 1];
__device__ int   g_cursor[NN];
__device__ int   g_colsrc[EE];
__device__ int   g_blocksum[1024];
// Split weights (bf16 hi/lo)
__device__ __nv_bfloat16 g_W0h[16384], g_W0l[16384];
__device__ __nv_bfloat16 g_W1h[16384], g_W1l[16384];
__device__ __nv_bfloat16 g_W2h[8192],  g_W2l[8192];

__device__ __forceinline__ void split_bf16(float v, __nv_bfloat16& h, __nv_bfloat16& l) {
    h = __float2bfloat16(v);
    l = __float2bfloat16(v - __bfloat162float(h));
}

// ---------------------------------------------------------------------------
// Weight split: W(fp32) -> Wh + Wl (bf16)
// ---------------------------------------------------------------------------
__global__ void split_w_kernel(const float* __restrict__ W, __nv_bfloat16* __restrict__ Wh,
                               __nv_bfloat16* __restrict__ Wl, int n) {
    int i = blockIdx.x * blockDim.x + threadIdx.x;
    if (i < n) {
        __nv_bfloat16 h, l;
        split_bf16(W[i], h, l);
        Wh[i] = h; Wl[i] = l;
    }
}

// in-degree histogram (cnt zero on entry; scan_add re-zeroes it each run)
__global__ void count_kernel(const int* __restrict__ dst, int* cnt, int e) {
    int i = blockIdx.x * blockDim.x + threadIdx.x;
    if (i < e) atomicAdd(&cnt[dst[i]], 1);
}

// dis = rsqrt(deg+1)
__global__ void dis_kernel(const int* __restrict__ cnt, float* __restrict__ dis, int n) {
    int i = blockIdx.x * blockDim.x + threadIdx.x;
    if (i < n) dis[i] = rsqrtf((float)cnt[i] + 1.0f);
}

// ---------------------------------------------------------------------------
// Multi-block exclusive scan
// ---------------------------------------------------------------------------
__global__ __launch_bounds__(1024) void scan_block_kernel(const int* __restrict__ cnt,
                                                          int* __restrict__ rowptr,
                                                          int* __restrict__ blocksum, int n) {
    __shared__ int wsum[32];
    const int tid = threadIdx.x, lane = tid & 31, wid = tid >> 5;
    int i = blockIdx.x * 1024 + tid;
    int v = (i < n) ? cnt[i] : 0;
    int x = v;
#pragma unroll
    for (int off = 1; off < 32; off <<= 1) {
        int t = __shfl_up_sync(0xffffffffu, x, off);
        if (lane >= off) x += t;
    }
    if (lane == 31) wsum[wid] = x;
    __syncthreads();
    if (wid == 0) {
        int w = wsum[lane];
#pragma unroll
        for (int off = 1; off < 32; off <<= 1) {
            int t = __shfl_up_sync(0xffffffffu, w, off);
            if (lane >= off) w += t;
        }
        wsum[lane] = w;
    }
    __syncthreads();
    int excl = x - v + (wid ? wsum[wid - 1] : 0);
    if (i < n) rowptr[i] = excl;
    if (tid == 1023) blocksum[blockIdx.x] = wsum[31];
}

__global__ void scan_carry_kernel(int* blocksum, int nb) {
    if (threadIdx.x == 0) {
        int acc = 0;
        for (int i = 0; i < nb; i++) { int v = blocksum[i]; blocksum[i] = acc; acc += v; }
    }
}

// add carries -> rowptr & cursor; re-zero cnt for next graph replay
__global__ void scan_add_kernel(int* __restrict__ rowptr, const int* __restrict__ blocksum,
                                int* __restrict__ cnt, int* __restrict__ cur, int n, int e) {
    int i = blockIdx.x * blockDim.x + threadIdx.x;
    if (i < n) {
        int r = rowptr[i] + blocksum[i >> 10];
        rowptr[i] = r;
        cur[i]    = r;
        cnt[i]    = 0;
    }
    if (i == 0) rowptr[n] = e;
}

__global__ void fill_kernel(const int* __restrict__ src, const int* __restrict__ dst,
                            int* __restrict__ cur, int* __restrict__ colsrc, int e) {
    int i = blockIdx.x * blockDim.x + threadIdx.x;
    if (i < e) {
        int pos = atomicAdd(&cur[dst[i]], 1);
        colsrc[pos] = src[i];
    }
}

// ---------------------------------------------------------------------------
// Tensor-core GEMM (bf16 split, fp32-equivalent accuracy):
//   C = A[M,128] @ W[128,BN] ; hs = C * dis[row]
// BM=128, 256 threads = 8 warps (4m x 2n), warp tile 32 x (BN/2).
// Full W (hi+lo) staged in smem ONCE; A split per 16-k stage, double-buffered.
// (R8-measured configuration: 522.8us total)
// ---------------------------------------------------------------------------
template <int BN>
__global__ __launch_bounds__(256, 2) void gemm_tc_kernel(
    const float* __restrict__ A,
    const __nv_bfloat16* __restrict__ Bh_g,
    const __nv_bfloat16* __restrict__ Bl_g,
    const float* __restrict__ dis,
    float* __restrict__ hs_out, int M)
{
    constexpr int WN  = BN / 2;
    constexpr int FN  = WN / 16;
    constexpr int LDA = 24;
    constexpr int LDB = BN + 8;
    constexpr int ASZ = 128 * LDA;

    extern __shared__ __align__(16) unsigned char smem_raw[];
    __nv_bfloat16* Ab = (__nv_bfloat16*)smem_raw;        // 4 buffers: h0,l0,h1,l1
    __nv_bfloat16* Bh = Ab + 4 * ASZ;
    __nv_bfloat16* Bl = Bh + 128 * LDB;

    const int tid  = threadIdx.x;
    const int wid  = tid >> 5;
    const int wm   = wid & 3;
    const int wn   = wid >> 2;
    const int row0 = blockIdx.x * 128;

    constexpr int ELEMS = 128 * BN;
    for (int e = tid * 8; e < ELEMS; e += 256 * 8) {
        int r = e / BN, c = e % BN;
        *(uint4*)&Bh[r * LDB + c] = *(const uint4*)&Bh_g[e];
        *(uint4*)&Bl[r * LDB + c] = *(const uint4*)&Bl_g[e];
    }

    wmma::fragment<wmma::accumulator, 16, 16, 16, float> acc[2][FN];
#pragma unroll
    for (int i = 0; i < 2; i++)
#pragma unroll
        for (int j = 0; j < FN; j++) wmma::fill_fragment(acc[i][j], 0.f);

    const int ar   = tid >> 1;
    const int ak   = (tid & 1) * 8;
    const int arow = row0 + ar;

    float4 v0 = make_float4(0.f, 0.f, 0.f, 0.f), v1 = v0;
    if (arow < M) {
        v0 = *(const float4*)(A + (size_t)arow * 128 + ak);
        v1 = *(const float4*)(A + (size_t)arow * 128 + ak + 4);
    }

    for (int s = 0; s < 8; s++) {
        __nv_bfloat16* pAh = Ab + (s & 1) * 2 * ASZ;
        __nv_bfloat16* pAl = pAh + ASZ;
        {
            __nv_bfloat16 h, l;
            split_bf16(v0.x, h, l); pAh[ar * LDA + ak + 0] = h; pAl[ar * LDA + ak + 0] = l;
            split_bf16(v0.y, h, l); pAh[ar * LDA + ak + 1] = h; pAl[ar * LDA + ak + 1] = l;
            split_bf16(v0.z, h, l); pAh[ar * LDA + ak + 2] = h; pAl[ar * LDA + ak + 2] = l;
            split_bf16(v0.w, h, l); pAh[ar * LDA + ak + 3] = h; pAl[ar * LDA + ak + 3] = l;
            split_bf16(v1.x, h, l); pAh[ar * LDA + ak + 4] = h; pAl[ar * LDA + ak + 4] = l;
            split_bf16(v1.y, h, l); pAh[ar * LDA + ak + 5] = h; pAl[ar * LDA + ak + 5] = l;
            split_bf16(v1.z, h, l); pAh[ar * LDA + ak + 6] = h; pAl[ar * LDA + ak + 6] = l;
            split_bf16(v1.w, h, l); pAh[ar * LDA + ak + 7] = h; pAl[ar * LDA + ak + 7] = l;
        }
        __syncthreads();

        if (s < 7 && arow < M) {
            v0 = *(const float4*)(A + (size_t)arow * 128 + (s + 1) * 16 + ak);
            v1 = *(const float4*)(A + (size_t)arow * 128 + (s + 1) * 16 + ak + 4);
        }

        wmma::fragment<wmma::matrix_a, 16, 16, 16, __nv_bfloat16, wmma::row_major> fa_h[2], fa_l[2];
#pragma unroll
        for (int i = 0; i < 2; i++) {
            wmma::load_matrix_sync(fa_h[i], pAh + (wm * 32 + i * 16) * LDA, LDA);
            wmma::load_matrix_sync(fa_l[i], pAl + (wm * 32 + i * 16) * LDA, LDA);
        }
#pragma unroll
        for (int j = 0; j < FN; j++) {
            wmma::fragment<wmma::matrix_b, 16, 16, 16, __nv_bfloat16, wmma::row_major> fb_h, fb_l;
            wmma::load_matrix_sync(fb_h, Bh + (s * 16) * LDB + wn * WN + j * 16, LDB);
            wmma::load_matrix_sync(fb_l, Bl + (s * 16) * LDB + wn * WN + j * 16, LDB);
#pragma unroll
            for (int i = 0; i < 2; i++) {
                wmma::mma_sync(acc[i][j], fa_h[i], fb_h, acc[i][j]);
                wmma::mma_sync(acc[i][j], fa_h[i], fb_l, acc[i][j]);
                wmma::mma_sync(acc[i][j], fa_l[i], fb_h, acc[i][j]);
            }
        }
    }

    __syncthreads();
    float* Cs = (float*)smem_raw;
#pragma unroll
    for (int i = 0; i < 2; i++)
#pragma unroll
        for (int j = 0; j < FN; j++)
            wmma::store_matrix_sync(Cs + (wm * 32 + i * 16) * BN + wn * WN + j * 16,
                                    acc[i][j], BN, wmma::mem_row_major);
    __syncthreads();

    constexpr int QB = BN / 4;
    for (int i = tid; i < 128 * QB; i += 256) {
        int r = i / QB, c = (i % QB) * 4;
        int row = row0 + r;
        if (row < M) {
            float dd = __ldg(dis + row);
            float4 o = *(float4*)&Cs[r * BN + c];
            o.x *= dd; o.y *= dd; o.z *= dd; o.w *= dd;
            *(float4*)(hs_out + (size_t)row * BN + c) = o;
        }
    }
}

// ---------------------------------------------------------------------------
// Aggregation + combine (CSR segment sum, no atomics):
//   outA[d,f] = relu( dis[d] * ( hs[d,f] + sum_{s in N(d)} hs[s,f] ) + b[f] )
// ---------------------------------------------------------------------------
__global__ __launch_bounds__(128) void agg_combine_kernel(
    const float* __restrict__ hs, const int* __restrict__ rowptr,
    const int* __restrict__ colsrc, const float* __restrict__ dis,
    const float* __restrict__ bias, float* __restrict__ outA, int n)
{
    constexpr int F = 128;
    int node = blockIdx.x;
    int f    = threadIdx.x;
    int beg  = __ldg(rowptr + node);
    int end  = __ldg(rowptr + node + 1);

    float s0 = __ldg(hs + (size_t)node * F + f);
    float s1 = 0.f, s2 = 0.f, s3 = 0.f;
    int p = beg;
    for (; p + 4 <= end; p += 4) {
        int i0 = __ldg(colsrc + p + 0);
        int i1 = __ldg(colsrc + p + 1);
        int i2 = __ldg(colsrc + p + 2);
        int i3 = __ldg(colsrc + p + 3);
        s0 += __ldg(hs + (size_t)i0 * F + f);
        s1 += __ldg(hs + (size_t)i1 * F + f);
        s2 += __ldg(hs + (size_t)i2 * F + f);
        s3 += __ldg(hs + (size_t)i3 * F + f);
    }
    for (; p < end; ++p)
        s0 += __ldg(hs + (size_t)__ldg(colsrc + p) * F + f);

    float sum = (s0 + s1) + (s2 + s3);
    outA[(size_t)node * F + f] = fmaxf(fmaf(__ldg(dis + node), sum, __ldg(bias + f)), 0.f);
}

// ---------------------------------------------------------------------------
// Fused final layer: aggregation + combine + relu + log_softmax (F=64)
// ---------------------------------------------------------------------------
__global__ __launch_bounds__(64) void agg_lsm_kernel(
    const float* __restrict__ hs, const int* __restrict__ rowptr,
    const int* __restrict__ colsrc, const float* __restrict__ dis,
    const float* __restrict__ bias, float* __restrict__ out, int n)
{
    constexpr int F = 64;
    int node = blockIdx.x;
    int f    = threadIdx.x;
    int lane = f & 31, w = f >> 5;
    int beg  = __ldg(rowptr + node);
    int end  = __ldg(rowptr + node + 1);

    float s0 = __ldg(hs + (size_t)node * F + f);
    float s1 = 0.f, s2 = 0.f, s3 = 0.f;
    int p = beg;
    for (; p + 4 <= end; p += 4) {
        int i0 = __ldg(colsrc + p + 0);
        int i1 = __ldg(colsrc + p + 1);
        int i2 = __ldg(colsrc + p + 2);
        int i3 = __ldg(colsrc + p + 3);
        s0 += __ldg(hs + (size_t)i0 * F + f);
        s1 += __ldg(hs + (size_t)i1 * F + f);
        s2 += __ldg(hs + (size_t)i2 * F + f);
        s3 += __ldg(hs + (size_t)i3 * F + f);
    }
    for (; p < end; ++p)
        s0 += __ldg(hs + (size_t)__ldg(colsrc + p) * F + f);

    float v = fmaxf(fmaf(__ldg(dis + node), (s0 + s1) + (s2 + s3), __ldg(bias + f)), 0.f);

    __shared__ float sred[2];
    float m = v;
#pragma unroll
    for (int off = 16; off > 0; off >>= 1)
        m = fmaxf(m, __shfl_xor_sync(0xffffffffu, m, off));
    if (lane == 0) sred[w] = m;
    __syncthreads();
    float M2 = fmaxf(sred[0], sred[1]);
    __syncthreads();

    float e = expf(v - M2);
    float s = e;
#pragma unroll
    for (int off = 16; off > 0; off >>= 1)
        s += __shfl_xor_sync(0xffffffffu, s, off);
    if (lane == 0) sred[w] = s;
    __syncthreads();
    float S = sred[0] + sred[1];

    out[(size_t)node * F + f] = v - M2 - logf(S);
}

// ---------------------------------------------------------------------------
// Launch (single stream; gemm0 is the 4th kernel launch for ncu capture)
// ---------------------------------------------------------------------------
extern "C" void kernel_launch(void* const* d_in, const int* in_sizes, int n_in,
                              void* d_out, int out_size) {
    const float* x  = (const float*)d_in[0];
    const int*   ei = (const int*)d_in[1];
    const float* W0 = (const float*)d_in[2];
    const float* b0 = (const float*)d_in[3];
    const float* W1 = (const float*)d_in[4];
    const float* b1 = (const float*)d_in[5];
    const float* W2 = (const float*)d_in[6];
    const float* b2 = (const float*)d_in[7];
    float* out = (float*)d_out;

    const int E = in_sizes[1] / 2;
    const int N = in_sizes[0] / DIM;
    const int* src = ei;
    const int* dst = ei + E;

    float *p_dis, *p_h, *p_a;
    int *p_cnt, *p_rowptr, *p_cursor, *p_colsrc, *p_blocksum;
    __nv_bfloat16 *p_W0h, *p_W0l, *p_W1h, *p_W1l, *p_W2h, *p_W2l;
    cudaGetSymbolAddress((void**)&p_dis,      g_dis);
    cudaGetSymbolAddress((void**)&p_h,        g_h);
    cudaGetSymbolAddress((void**)&p_a,        g_a);
    cudaGetSymbolAddress((void**)&p_cnt,      g_cnt);
    cudaGetSymbolAddress((void**)&p_rowptr,   g_rowptr);
    cudaGetSymbolAddress((void**)&p_cursor,   g_cursor);
    cudaGetSymbolAddress((void**)&p_colsrc,   g_colsrc);
    cudaGetSymbolAddress((void**)&p_blocksum, g_blocksum);
    cudaGetSymbolAddress((void**)&p_W0h, g_W0h); cudaGetSymbolAddress((void**)&p_W0l, g_W0l);
    cudaGetSymbolAddress((void**)&p_W1h, g_W1h); cudaGetSymbolAddress((void**)&p_W1l, g_W1l);
    cudaGetSymbolAddress((void**)&p_W2h, g_W2h); cudaGetSymbolAddress((void**)&p_W2l, g_W2l);

    const int smem128 = (4 * 128 * 24 + 2 * 128 * 136) * 2;   // 94208 B
    const int smem64  = (4 * 128 * 24 + 2 * 128 * 72)  * 2;   // 61440 B
    cudaFuncSetAttribute(gemm_tc_kernel<128>, cudaFuncAttributeMaxDynamicSharedMemorySize, smem128);
    cudaFuncSetAttribute(gemm_tc_kernel<64>,  cudaFuncAttributeMaxDynamicSharedMemorySize, smem64);

    const int T = 256;
    const int nb = (N + 1023) / 1024;
    const int gemm_blocks = (N + 127) / 128;

    // 1-3: gemm0 prerequisites
    count_kernel<<<(E + T - 1) / T, T>>>(dst, p_cnt, E);                     // 1
    dis_kernel<<<(N + T - 1) / T, T>>>(p_cnt, p_dis, N);                     // 2
    split_w_kernel<<<64, 256>>>(W0, p_W0h, p_W0l, 16384);                    // 3

    // 4: layer-0 GEMM (ncu captures the 4th launch)
    gemm_tc_kernel<128><<<gemm_blocks, 256, smem128>>>(x, p_W0h, p_W0l,
                                                       p_dis, p_h, N);       // 4

    // remaining weight splits + CSR build
    split_w_kernel<<<64, 256>>>(W1, p_W1h, p_W1l, 16384);
    split_w_kernel<<<32, 256>>>(W2, p_W2h, p_W2l, 8192);
    scan_block_kernel<<<nb, 1024>>>(p_cnt, p_rowptr, p_blocksum, N);
    scan_carry_kernel<<<1, 32>>>(p_blocksum, nb);
    scan_add_kernel<<<(N + T - 1) / T, T>>>(p_rowptr, p_blocksum, p_cnt, p_cursor, N, E);
    fill_kernel<<<(E + T - 1) / T, T>>>(src, dst, p_cursor, p_colsrc, E);

    // Layer 0 combine
    agg_combine_kernel<<<N, 128>>>(p_h, p_rowptr, p_colsrc, p_dis, b0, p_a, N);

    // Layer 1
    gemm_tc_kernel<128><<<gemm_blocks, 256, smem128>>>(p_a, p_W1h, p_W1l, p_dis, p_h, N);
    agg_combine_kernel<<<N, 128>>>(p_h, p_rowptr, p_colsrc, p_dis, b1, p_a, N);

    // Layer 2 (64 cols) + fused log_softmax
    gemm_tc_kernel<64><<<gemm_blocks, 256, smem64>>>(p_a, p_W2h, p_W2l, p_dis, p_h, N);
    agg_lsm_kernel<<<N, 64>>>(p_h, p_rowptr, p_colsrc, p_dis, b2, out, N);
}